// round 4
// baseline (speedup 1.0000x reference)
#include <cuda_runtime.h>
#include <cuda_fp16.h>
#include <cstdint>

#define T_STEPS 512
#define B_DIM   256
#define H_DIM   256
#define N3H     768
#define M_ROWS  (T_STEPS * B_DIM)

// ---------------- scratch (device globals; no allocations allowed) ----------
__device__ float g_gi[(size_t)M_ROWS * N3H];   // [T*B, 3H] fp32, ~402 MB
__device__ uint2 g_whp[128 * 384];             // Wh packed fp16: [k2][pair]
__device__ unsigned int g_rst_viol;            // bit0: not-int32, bit1: not-float32

// ---------------- resets dtype detection ------------------------------------
__global__ void rst_init_kernel() { g_rst_viol = 0u; }

// Probe the first 131072 bytes (safe under every interpretation: uint8 total
// is T*B = 131072 bytes). If all 32-bit words are 0/1 -> int32. If all words
// are 0/0x3F800000 -> float32. Otherwise raw bytes (uint8 bool).
__global__ void rst_detect_kernel(const unsigned int* __restrict__ r) {
    int i = blockIdx.x * blockDim.x + threadIdx.x;   // 0..32767
    unsigned int w = r[i];
    unsigned int v = 0;
    if (w != 0u && w != 1u)          v |= 1u;  // violates int32
    if (w != 0u && w != 0x3F800000u) v |= 2u;  // violates float32
    if (v) atomicOr(&g_rst_viol, v);
}

__device__ __forceinline__ bool read_reset(const void* r, unsigned int viol, size_t idx) {
    if (!(viol & 1u)) return ((const int*)r)[idx] != 0;
    if (!(viol & 2u)) return ((const float*)r)[idx] != 0.0f;
    return ((const unsigned char*)r)[idx] != 0;
}

// ---------------- kernel 0: pack Wh -> fp16 pairs ---------------------------
// g_whp[k2*384+p].x = half2(Wh[2k2  ][2p], Wh[2k2  ][2p+1])
// g_whp[k2*384+p].y = half2(Wh[2k2+1][2p], Wh[2k2+1][2p+1])
__global__ void pack_wh_kernel(const float* __restrict__ Wh) {
    int idx = blockIdx.x * blockDim.x + threadIdx.x;
    if (idx >= 128 * 384) return;
    int k2 = idx / 384, p = idx - k2 * 384;
    int k = k2 * 2, c = p * 2;
    __half2 hx = __floats2half2_rn(Wh[(size_t)k * N3H + c],       Wh[(size_t)k * N3H + c + 1]);
    __half2 hy = __floats2half2_rn(Wh[(size_t)(k + 1) * N3H + c], Wh[(size_t)(k + 1) * N3H + c + 1]);
    uint2 w;
    w.x = *(unsigned int*)&hx;
    w.y = *(unsigned int*)&hy;
    g_whp[idx] = w;
}

// ---------------- kernel A: gi = ins @ Wi + bi  (fp32 tiled SGEMM) ----------
#define BM 128
#define BN 64
#define BK 16

__global__ __launch_bounds__(256) void gemm_gi_kernel(
    const float* __restrict__ A,     // ins viewed [M_ROWS][H_DIM]
    const float* __restrict__ Bw,    // Wi [H_DIM][N3H]
    const float* __restrict__ bias)  // bi [N3H]
{
    __shared__ float As[BK][BM];     // transposed A tile
    __shared__ float Bs[BK][BN];

    int tid = threadIdx.x;
    int tx = tid & 15;               // 0..15 -> 4 output cols each
    int ty = tid >> 4;               // 0..15 -> 8 output rows each
    int row0 = blockIdx.y * BM;
    int col0 = blockIdx.x * BN;

    float acc[8][4];
#pragma unroll
    for (int r = 0; r < 8; r++)
#pragma unroll
        for (int c = 0; c < 4; c++) acc[r][c] = 0.f;

    for (int k0 = 0; k0 < H_DIM; k0 += BK) {
#pragma unroll
        for (int i = 0; i < 2; i++) {
            int idx = tid + i * 256;            // 0..511
            int ar = idx & 127, ac4 = idx >> 7; // ac4 0..3
            float4 v = *(const float4*)(A + (size_t)(row0 + ar) * H_DIM + k0 + ac4 * 4);
            As[ac4 * 4 + 0][ar] = v.x;
            As[ac4 * 4 + 1][ar] = v.y;
            As[ac4 * 4 + 2][ar] = v.z;
            As[ac4 * 4 + 3][ar] = v.w;
        }
        {
            int br = tid >> 4, bc4 = tid & 15;
            float4 v = *(const float4*)(Bw + (size_t)(k0 + br) * N3H + col0 + bc4 * 4);
            *(float4*)&Bs[br][bc4 * 4] = v;
        }
        __syncthreads();

#pragma unroll
        for (int kk = 0; kk < BK; kk++) {
            float4 a0 = *(const float4*)&As[kk][ty * 8];
            float4 a1 = *(const float4*)&As[kk][ty * 8 + 4];
            float4 b  = *(const float4*)&Bs[kk][tx * 4];
            float av[8] = {a0.x, a0.y, a0.z, a0.w, a1.x, a1.y, a1.z, a1.w};
            float bv[4] = {b.x, b.y, b.z, b.w};
#pragma unroll
            for (int r = 0; r < 8; r++)
#pragma unroll
                for (int c = 0; c < 4; c++)
                    acc[r][c] = fmaf(av[r], bv[c], acc[r][c]);
        }
        __syncthreads();
    }

    float4 bias4 = *(const float4*)(bias + col0 + tx * 4);
#pragma unroll
    for (int r = 0; r < 8; r++) {
        float4 o;
        o.x = acc[r][0] + bias4.x;
        o.y = acc[r][1] + bias4.y;
        o.z = acc[r][2] + bias4.z;
        o.w = acc[r][3] + bias4.w;
        *(float4*)(g_gi + (size_t)(row0 + ty * 8 + r) * N3H + col0 + tx * 4) = o;
    }
}

// ---------------- kernel B: sequential GRU scan -----------------------------
// One CTA owns 2 batch rows for all 512 steps. No inter-CTA sync needed.
// Per step: gh = h @ Wh (fp16 weights, fp32 accum), then gate math.
// First KC2 k-pairs of packed Wh are cached in SMEM; rest streamed from L2.
#define SCAN_THREADS 384
#define KC2 64
#define SMEM_WH_BYTES (KC2 * 384 * 8)                      // 196608
#define SMEM_BYTES (SMEM_WH_BYTES + 6144 + 6144 + 2048)    // 210944

__global__ __launch_bounds__(SCAN_THREADS) void scan_kernel(
    const void* __restrict__ resets,           // [T][B], dtype auto-detected
    const float* __restrict__ carry,           // [B][H]
    const float* __restrict__ bhn,             // [H]
    float* __restrict__ out)                   // [T][B][H]
{
    extern __shared__ unsigned char smraw[];
    uint2* whS = (uint2*)smraw;                              // KC2*384 uint2
    float* giS = (float*)(smraw + SMEM_WH_BYTES);            // [2][768]
    float* ghS = (float*)(smraw + SMEM_WH_BYTES + 6144);     // [2][768]
    float* hS  = (float*)(smraw + SMEM_WH_BYTES + 12288);    // [2][256]

    const int tid = threadIdx.x;
    const int b0 = blockIdx.x * 2;
    const uint2* __restrict__ whp = g_whp;
    const unsigned int viol = g_rst_viol;

    // stage Wh cache
    for (int i = tid; i < KC2 * 384; i += SCAN_THREADS) whS[i] = whp[i];
    // init carry with step-0 reset applied
    for (int o = tid; o < 2 * H_DIM; o += SCAN_THREADS) {
        int r = o >> 8, i = o & 255;
        float h = carry[(size_t)(b0 + r) * H_DIM + i];
        if (read_reset(resets, viol, b0 + r)) h = 0.f;
        hS[r * H_DIM + i] = h;
    }
    __syncthreads();

    const float2* h0p = (const float2*)(hS);
    const float2* h1p = (const float2*)(hS + H_DIM);
    float2* gh0p = (float2*)ghS;
    float2* gh1p = (float2*)(ghS + N3H);

    for (int t = 0; t < T_STEPS; t++) {
        // prefetch gi for this step (held in regs until after the GEMM)
        float4 g4 = *(const float4*)(g_gi + ((size_t)t * B_DIM + b0) * N3H + tid * 4);

        float a00 = 0.f, a01 = 0.f, a10 = 0.f, a11 = 0.f;

#pragma unroll 8
        for (int k2 = 0; k2 < KC2; k2++) {
            uint2 w = whS[k2 * 384 + tid];
            float2 h0 = h0p[k2];
            float2 h1 = h1p[k2];
            float2 wx = __half22float2(*(const __half2*)&w.x);  // row 2k2:   cols 2tid, 2tid+1
            float2 wy = __half22float2(*(const __half2*)&w.y);  // row 2k2+1: cols 2tid, 2tid+1
            a00 = fmaf(wx.x, h0.x, a00); a00 = fmaf(wy.x, h0.y, a00);
            a01 = fmaf(wx.y, h0.x, a01); a01 = fmaf(wy.y, h0.y, a01);
            a10 = fmaf(wx.x, h1.x, a10); a10 = fmaf(wy.x, h1.y, a10);
            a11 = fmaf(wx.y, h1.x, a11); a11 = fmaf(wy.y, h1.y, a11);
        }
#pragma unroll 8
        for (int k2 = KC2; k2 < 128; k2++) {
            uint2 w = __ldg(&whp[k2 * 384 + tid]);
            float2 h0 = h0p[k2];
            float2 h1 = h1p[k2];
            float2 wx = __half22float2(*(const __half2*)&w.x);
            float2 wy = __half22float2(*(const __half2*)&w.y);
            a00 = fmaf(wx.x, h0.x, a00); a00 = fmaf(wy.x, h0.y, a00);
            a01 = fmaf(wx.y, h0.x, a01); a01 = fmaf(wy.y, h0.y, a01);
            a10 = fmaf(wx.x, h1.x, a10); a10 = fmaf(wy.x, h1.y, a10);
            a11 = fmaf(wx.y, h1.x, a11); a11 = fmaf(wy.y, h1.y, a11);
        }

        gh0p[tid] = make_float2(a00, a01);   // row0 cols 2tid, 2tid+1
        gh1p[tid] = make_float2(a10, a11);   // row1 cols 2tid, 2tid+1
        *(float4*)(giS + tid * 4) = g4;
        __syncthreads();

#pragma unroll
        for (int u = 0; u < 2; u++) {
            int o = tid + u * SCAN_THREADS;
            if (o < 2 * H_DIM) {
                int r = o >> 8, i = o & 255;
                const float* gir = giS + r * N3H;
                const float* ghr = ghS + r * N3H;
                float xr = gir[i], xz = gir[H_DIM + i], xn = gir[2 * H_DIM + i];
                float hr = ghr[i], hz = ghr[H_DIM + i], hn = ghr[2 * H_DIM + i];
                float rg = 1.f / (1.f + expf(-(xr + hr)));
                float zg = 1.f / (1.f + expf(-(xz + hz)));
                float ng = tanhf(xn + rg * (hn + bhn[i]));
                float hprev = hS[r * H_DIM + i];
                float hnew = (1.f - zg) * ng + zg * hprev;
                out[((size_t)t * B_DIM + b0 + r) * H_DIM + i] = hnew;
                if (t + 1 < T_STEPS && read_reset(resets, viol, (size_t)(t + 1) * B_DIM + b0 + r))
                    hnew = 0.f;
                hS[r * H_DIM + i] = hnew;
            }
        }
        __syncthreads();
    }
}

// ---------------- launcher ---------------------------------------------------
extern "C" void kernel_launch(void* const* d_in, const int* in_sizes, int n_in,
                              void* d_out, int out_size) {
    (void)in_sizes; (void)n_in; (void)out_size;
    const float* ins    = (const float*)d_in[0];
    const void*  resets = (const void*)d_in[1];
    const float* carry  = (const float*)d_in[2];
    const float* Wi     = (const float*)d_in[3];
    const float* bi     = (const float*)d_in[4];
    const float* Wh     = (const float*)d_in[5];
    const float* bhn    = (const float*)d_in[6];
    float*       out    = (float*)d_out;

    // 0) detect resets dtype (int32 / float32 / uint8)
    rst_init_kernel<<<1, 1>>>();
    rst_detect_kernel<<<32768 / 256, 256>>>((const unsigned int*)resets);

    // 1) pack Wh -> fp16 pairs
    pack_wh_kernel<<<96, 512>>>(Wh);

    // 2) gi = ins @ Wi + bi for all T*B rows
    dim3 ggrid(N3H / BN, M_ROWS / BM);
    gemm_gi_kernel<<<ggrid, 256>>>(ins, Wi, bi);

    // 3) sequential scan, 2 batch rows per CTA
    cudaFuncSetAttribute(scan_kernel, cudaFuncAttributeMaxDynamicSharedMemorySize, SMEM_BYTES);
    scan_kernel<<<B_DIM / 2, SCAN_THREADS, SMEM_BYTES>>>(resets, carry, bhn, out);
}

// round 5
// speedup vs baseline: 1.4633x; 1.4633x over previous
#include <cuda_runtime.h>
#include <cuda_fp16.h>
#include <cstdint>

#define T_STEPS 512
#define B_DIM   256
#define H_DIM   256
#define N3H     768
#define M_ROWS  (T_STEPS * B_DIM)

// ---------------- scratch (device globals; no allocations allowed) ----------
__device__ float g_gi[(size_t)M_ROWS * N3H];            // [T*B, 3H] fp32
__device__ unsigned short g_a16[(size_t)M_ROWS * H_DIM]; // ins as fp16
__device__ unsigned short g_wi16t[N3H * H_DIM];          // Wi transposed [n][k] fp16
__device__ uint2 g_whq[H_DIM * 192];                     // Wh fp16: [k][cg] = 4 cols
__device__ unsigned int g_rst_viol;

// ---------------- resets dtype detection ------------------------------------
__global__ void rst_init_kernel() { g_rst_viol = 0u; }
__global__ void rst_detect_kernel(const unsigned int* __restrict__ r) {
    int i = blockIdx.x * blockDim.x + threadIdx.x;   // 0..32767
    unsigned int w = r[i];
    unsigned int v = 0;
    if (w != 0u && w != 1u)          v |= 1u;
    if (w != 0u && w != 0x3F800000u) v |= 2u;
    if (v) atomicOr(&g_rst_viol, v);
}
__device__ __forceinline__ bool read_reset(const void* r, unsigned int viol, size_t idx) {
    if (!(viol & 1u)) return ((const int*)r)[idx] != 0;
    if (!(viol & 2u)) return ((const float*)r)[idx] != 0.0f;
    return ((const unsigned char*)r)[idx] != 0;
}

// ---------------- pack kernels ----------------------------------------------
__global__ void pack_a16_kernel(const float* __restrict__ ins) {
    size_t idx4 = (size_t)blockIdx.x * blockDim.x + threadIdx.x;  // groups of 4
    if (idx4 >= (size_t)M_ROWS * H_DIM / 4) return;
    float4 v = *(const float4*)(ins + idx4 * 4);
    __half2 lo = __floats2half2_rn(v.x, v.y);
    __half2 hi = __floats2half2_rn(v.z, v.w);
    uint2 o; o.x = *(unsigned int*)&lo; o.y = *(unsigned int*)&hi;
    ((uint2*)g_a16)[idx4] = o;
}
__global__ void pack_wi16t_kernel(const float* __restrict__ Wi) {
    int idx = blockIdx.x * blockDim.x + threadIdx.x;  // 0..196607
    if (idx >= N3H * H_DIM) return;
    int n = idx >> 8, k = idx & 255;
    g_wi16t[idx] = __half_as_ushort(__float2half_rn(Wi[(size_t)k * N3H + n]));
}
__global__ void pack_whq_kernel(const float* __restrict__ Wh) {
    int idx = blockIdx.x * blockDim.x + threadIdx.x;  // 0..49151
    if (idx >= H_DIM * 192) return;
    int k = idx / 192, cg = idx - k * 192;
    const float* w = Wh + (size_t)k * N3H + cg * 4;
    __half2 lo = __floats2half2_rn(w[0], w[1]);
    __half2 hi = __floats2half2_rn(w[2], w[3]);
    uint2 o; o.x = *(unsigned int*)&lo; o.y = *(unsigned int*)&hi;
    g_whq[idx] = o;
}

// ---------------- kernel A: gi = ins @ Wi + bi  (fp16 tensor mma) -----------
__device__ __forceinline__ unsigned int smem_u32(const void* p) {
    return (unsigned int)__cvta_generic_to_shared(p);
}
__device__ __forceinline__ void ldm_x4(unsigned int& r0, unsigned int& r1,
                                       unsigned int& r2, unsigned int& r3, unsigned int a) {
    asm volatile("ldmatrix.sync.aligned.m8n8.x4.shared.b16 {%0,%1,%2,%3}, [%4];"
                 : "=r"(r0), "=r"(r1), "=r"(r2), "=r"(r3) : "r"(a));
}
__device__ __forceinline__ void ldm_x2(unsigned int& r0, unsigned int& r1, unsigned int a) {
    asm volatile("ldmatrix.sync.aligned.m8n8.x2.shared.b16 {%0,%1}, [%2];"
                 : "=r"(r0), "=r"(r1) : "r"(a));
}
__device__ __forceinline__ void mma16816(float& d0, float& d1, float& d2, float& d3,
                                         unsigned int a0, unsigned int a1, unsigned int a2,
                                         unsigned int a3, unsigned int b0, unsigned int b1) {
    asm volatile("mma.sync.aligned.m16n8k16.row.col.f32.f16.f16.f32 "
                 "{%0,%1,%2,%3}, {%4,%5,%6,%7}, {%8,%9}, {%0,%1,%2,%3};"
                 : "+f"(d0), "+f"(d1), "+f"(d2), "+f"(d3)
                 : "r"(a0), "r"(a1), "r"(a2), "r"(a3), "r"(b0), "r"(b1));
}

#define GK 32
#define ASTRIDE 40

__global__ __launch_bounds__(256) void gemm_gi_mma(const float* __restrict__ bias) {
    __shared__ __half As[128][ASTRIDE];
    __shared__ __half Bs[128][ASTRIDE];

    const __half* A16 = (const __half*)g_a16;
    const __half* B16 = (const __half*)g_wi16t;

    int tid = threadIdx.x, warp = tid >> 5, lane = tid & 31;
    int m0 = blockIdx.y * 128, n0 = blockIdx.x * 128;
    int wm = (warp >> 2) * 64, wn = (warp & 3) * 32;

    float acc[4][4][4];
#pragma unroll
    for (int i = 0; i < 4; i++)
#pragma unroll
        for (int j = 0; j < 4; j++)
#pragma unroll
            for (int q = 0; q < 4; q++) acc[i][j][q] = 0.f;

    int lr = tid >> 1, lq = (tid & 1) * 16;
    for (int kt = 0; kt < H_DIM; kt += GK) {
        {
            const uint4* sa = (const uint4*)(A16 + (size_t)(m0 + lr) * H_DIM + kt + lq);
            uint4 v0 = sa[0], v1 = sa[1];
            *(uint4*)&As[lr][lq] = v0; *(uint4*)&As[lr][lq + 8] = v1;
            const uint4* sb = (const uint4*)(B16 + (size_t)(n0 + lr) * H_DIM + kt + lq);
            uint4 w0 = sb[0], w1 = sb[1];
            *(uint4*)&Bs[lr][lq] = w0; *(uint4*)&Bs[lr][lq + 8] = w1;
        }
        __syncthreads();
#pragma unroll
        for (int ks = 0; ks < 2; ks++) {
            int kl = ks * 16;
            unsigned int a[4][4], b[4][2];
#pragma unroll
            for (int mf = 0; mf < 4; mf++) {
                int row = wm + mf * 16 + (lane & 15);
                int col = kl + (lane >> 4) * 8;
                ldm_x4(a[mf][0], a[mf][1], a[mf][2], a[mf][3], smem_u32(&As[row][col]));
            }
#pragma unroll
            for (int nf = 0; nf < 4; nf++) {
                int row = wn + nf * 8 + (lane & 7);
                int col = kl + ((lane >> 3) & 1) * 8;
                ldm_x2(b[nf][0], b[nf][1], smem_u32(&Bs[row][col]));
            }
#pragma unroll
            for (int mf = 0; mf < 4; mf++)
#pragma unroll
                for (int nf = 0; nf < 4; nf++)
                    mma16816(acc[mf][nf][0], acc[mf][nf][1], acc[mf][nf][2], acc[mf][nf][3],
                             a[mf][0], a[mf][1], a[mf][2], a[mf][3], b[nf][0], b[nf][1]);
        }
        __syncthreads();
    }

    int g = lane >> 2, c = (lane & 3) * 2;
#pragma unroll
    for (int mf = 0; mf < 4; mf++)
#pragma unroll
        for (int nf = 0; nf < 4; nf++) {
            int row = m0 + wm + mf * 16 + g;
            int col = n0 + wn + nf * 8 + c;
            float2 b2 = *(const float2*)(bias + col);
            float2 o0, o1;
            o0.x = acc[mf][nf][0] + b2.x; o0.y = acc[mf][nf][1] + b2.y;
            o1.x = acc[mf][nf][2] + b2.x; o1.y = acc[mf][nf][3] + b2.y;
            *(float2*)(g_gi + (size_t)row * N3H + col) = o0;
            *(float2*)(g_gi + (size_t)(row + 8) * N3H + col) = o1;
        }
}

// ---------------- kernel B: sequential GRU scan (HFMA2) ---------------------
// 128 CTAs x 384 threads; CTA owns 2 batch rows for all 512 steps.
// Threads: kh = tid/192 (k-half), cg = tid%192 (4 output cols).
// Cached k-rows (bit6==0) in SMEM; streamed rows (bit6==1) from L2.
#define SCAN_THREADS 384
#define SMEM_WH   (128 * 192 * 8)               // 196608
#define SMEM_GI   6144
#define SMEM_GH   (4 * N3H * 4)                 // 12288
#define SMEM_H    2048
#define SMEM_H2B  2048
#define SMEM_BYTES (SMEM_WH + SMEM_GI + SMEM_GH + SMEM_H + SMEM_H2B)  // 219136

template<bool STREAM>
__device__ __forceinline__ void kblock32(
    const uint2* __restrict__ w0, const __half2* __restrict__ hb0,
    const __half2* __restrict__ hb1,
    __half2& a00, __half2& a01, __half2& a10, __half2& a11)
{
#pragma unroll 8
    for (int j = 0; j < 32; j++) {
        uint2 w = STREAM ? __ldg(w0 + (size_t)j * 192) : w0[(size_t)j * 192];
        __half2 w01 = *(__half2*)&w.x;
        __half2 w23 = *(__half2*)&w.y;
        __half2 h0 = hb0[j], h1 = hb1[j];
        a00 = __hfma2(w01, h0, a00);
        a01 = __hfma2(w23, h0, a01);
        a10 = __hfma2(w01, h1, a10);
        a11 = __hfma2(w23, h1, a11);
    }
}

__global__ __launch_bounds__(SCAN_THREADS) void scan_kernel(
    const void* __restrict__ resets,
    const float* __restrict__ carry,
    const float* __restrict__ bhn,
    float* __restrict__ out)
{
    extern __shared__ unsigned char smraw[];
    uint2*   whS  = (uint2*)smraw;
    float*   giS  = (float*)(smraw + SMEM_WH);
    float*   ghP  = (float*)(smraw + SMEM_WH + SMEM_GI);          // [kh][row][768]
    float*   hS   = (float*)(smraw + SMEM_WH + SMEM_GI + SMEM_GH);
    __half2* h2b0 = (__half2*)(smraw + SMEM_WH + SMEM_GI + SMEM_GH + SMEM_H);
    __half2* h2b1 = h2b0 + H_DIM;

    const int tid = threadIdx.x;
    const int b0 = blockIdx.x * 2;
    const unsigned int viol = g_rst_viol;
    const int kh = (tid >= 192) ? 1 : 0;
    const int cg = tid - kh * 192;

    // stage cached Wh rows: k with bit6==0, smem row k' = ((k>>7)<<6)|(k&63)
    for (int i = tid; i < 128 * 192; i += SCAN_THREADS) {
        int kp = i / 192, c = i - kp * 192;
        int k = ((kp >> 6) << 7) | (kp & 63);
        whS[i] = g_whq[(size_t)k * 192 + c];
    }
    for (int o = tid; o < 2 * H_DIM; o += SCAN_THREADS) {
        int r = o >> 8, i = o & 255;
        float h = carry[(size_t)(b0 + r) * H_DIM + i];
        if (read_reset(resets, viol, b0 + r)) h = 0.f;
        hS[r * H_DIM + i] = h;
        (r ? h2b1 : h2b0)[i] = __float2half2_rn(h);
    }
    __syncthreads();

    const uint2* wsA = whS + (size_t)(kh * 64) * 192 + cg;              // cached 64 rows
    const uint2* wgB = g_whq + (size_t)(kh * 128 + 64) * 192 + cg;      // streamed 64 rows
    const int kb = kh * 128;
    float* gp = ghP + (size_t)(kh * 2) * N3H + cg * 4;

    for (int t = 0; t < T_STEPS; t++) {
        float4 g4 = *(const float4*)(g_gi + ((size_t)t * B_DIM + b0) * N3H + tid * 4);

        const __half2 z2 = __float2half2_rn(0.f);
        __half2 a00, a01, a10, a11;
        float f0 = 0.f, f1 = 0.f, f2 = 0.f, f3 = 0.f, f4 = 0.f, f5 = 0.f, f6 = 0.f, f7 = 0.f;

#define FLUSH() do { \
        float2 u; \
        u = __half22float2(a00); f0 += u.x; f1 += u.y; \
        u = __half22float2(a01); f2 += u.x; f3 += u.y; \
        u = __half22float2(a10); f4 += u.x; f5 += u.y; \
        u = __half22float2(a11); f6 += u.x; f7 += u.y; } while (0)

        a00 = z2; a01 = z2; a10 = z2; a11 = z2;
        kblock32<false>(wsA,              h2b0 + kb,      h2b1 + kb,      a00, a01, a10, a11);
        FLUSH(); a00 = z2; a01 = z2; a10 = z2; a11 = z2;
        kblock32<false>(wsA + 32 * 192,   h2b0 + kb + 32, h2b1 + kb + 32, a00, a01, a10, a11);
        FLUSH(); a00 = z2; a01 = z2; a10 = z2; a11 = z2;
        kblock32<true >(wgB,              h2b0 + kb + 64, h2b1 + kb + 64, a00, a01, a10, a11);
        FLUSH(); a00 = z2; a01 = z2; a10 = z2; a11 = z2;
        kblock32<true >(wgB + 32 * 192,   h2b0 + kb + 96, h2b1 + kb + 96, a00, a01, a10, a11);
        FLUSH();
#undef FLUSH

        *(float4*)gp         = make_float4(f0, f1, f2, f3);   // row 0, cols 4cg..
        *(float4*)(gp + N3H) = make_float4(f4, f5, f6, f7);   // row 1
        *(float4*)(giS + tid * 4) = g4;
        __syncthreads();

#pragma unroll
        for (int u = 0; u < 2; u++) {
            int o = tid + u * SCAN_THREADS;
            if (o < 2 * H_DIM) {
                int r = o >> 8, i = o & 255;
                const float* gir = giS + r * N3H;
                const float* gh0 = ghP + r * N3H;            // kh=0 plane
                const float* gh1 = ghP + (2 + r) * N3H;      // kh=1 plane
                float xr = gir[i], xz = gir[H_DIM + i], xn = gir[2 * H_DIM + i];
                float hr = gh0[i] + gh1[i];
                float hz = gh0[H_DIM + i] + gh1[H_DIM + i];
                float hn = gh0[2 * H_DIM + i] + gh1[2 * H_DIM + i];
                float rg = 1.f / (1.f + expf(-(xr + hr)));
                float zg = 1.f / (1.f + expf(-(xz + hz)));
                float ng = tanhf(xn + rg * (hn + bhn[i]));
                float hprev = hS[r * H_DIM + i];
                float hnew = (1.f - zg) * ng + zg * hprev;
                out[((size_t)t * B_DIM + b0 + r) * H_DIM + i] = hnew;
                if (t + 1 < T_STEPS && read_reset(resets, viol, (size_t)(t + 1) * B_DIM + b0 + r))
                    hnew = 0.f;
                hS[r * H_DIM + i] = hnew;
                (r ? h2b1 : h2b0)[i] = __float2half2_rn(hnew);
            }
        }
        __syncthreads();
    }
}

// ---------------- launcher ---------------------------------------------------
extern "C" void kernel_launch(void* const* d_in, const int* in_sizes, int n_in,
                              void* d_out, int out_size) {
    (void)in_sizes; (void)n_in; (void)out_size;
    const float* ins    = (const float*)d_in[0];
    const void*  resets = (const void*)d_in[1];
    const float* carry  = (const float*)d_in[2];
    const float* Wi     = (const float*)d_in[3];
    const float* bi     = (const float*)d_in[4];
    const float* Wh     = (const float*)d_in[5];
    const float* bhn    = (const float*)d_in[6];
    float*       out    = (float*)d_out;

    rst_init_kernel<<<1, 1>>>();
    rst_detect_kernel<<<32768 / 256, 256>>>((const unsigned int*)resets);

    pack_a16_kernel<<<(M_ROWS * H_DIM / 4 + 255) / 256, 256>>>(ins);
    pack_wi16t_kernel<<<(N3H * H_DIM + 255) / 256, 256>>>(Wi);
    pack_whq_kernel<<<(H_DIM * 192 + 255) / 256, 256>>>(Wh);

    dim3 ggrid(N3H / 128, M_ROWS / 128);
    gemm_gi_mma<<<ggrid, 256>>>(bi);

    cudaFuncSetAttribute(scan_kernel, cudaFuncAttributeMaxDynamicSharedMemorySize, SMEM_BYTES);
    scan_kernel<<<B_DIM / 2, SCAN_THREADS, SMEM_BYTES>>>(resets, carry, bhn, out);
}